// round 8
// baseline (speedup 1.0000x reference)
#include <cuda_runtime.h>
#include <cuda_bf16.h>
#include <math.h>
#include <stdint.h>

#define ALPHA_SLOPE 0.2f
#define NEG_INF_F   -9000000000000000.0f

#define BB    16
#define NN    1024
#define FIN   1024
#define FOUT  512
#define MTOT  (BB*NN)        // 16384

// ---------------- scratch (static device globals) ---------------------------
__device__ __nv_bfloat16 d_x_hi [(size_t)MTOT * FIN];
__device__ __nv_bfloat16 d_x_lo [(size_t)MTOT * FIN];
__device__ __nv_bfloat16 d_wt_hi[(size_t)FOUT * FIN];      // W^T [512][1024]
__device__ __nv_bfloat16 d_wt_lo[(size_t)FOUT * FIN];
__device__ __nv_bfloat16 d_fcw_hi[(size_t)FOUT * 2 * FOUT];
__device__ __nv_bfloat16 d_fcw_lo[(size_t)FOUT * 2 * FOUT];
__device__ __nv_bfloat16 d_h_hi [(size_t)MTOT * FOUT];
__device__ __nv_bfloat16 d_h_lo [(size_t)MTOT * FOUT];
__device__ __nv_bfloat16 d_ht_hi[(size_t)BB * FOUT * NN];  // h^T per batch [512][1024]
__device__ __nv_bfloat16 d_ht_lo[(size_t)BB * FOUT * NN];
__device__ __nv_bfloat16 d_att_hi[(size_t)MTOT * NN];
__device__ __nv_bfloat16 d_att_lo[(size_t)MTOT * NN];
__device__ __nv_bfloat16 d_agg_hi[(size_t)MTOT * FOUT];
__device__ __nv_bfloat16 d_agg_lo[(size_t)MTOT * FOUT];
__device__ float d_f1 [MTOT];
__device__ float d_f2 [MTOT];
__device__ float d_inv[MTOT];

// ---------------- helpers ----------------------------------------------------
__device__ __forceinline__ uint32_t smem_u32(const void* p) {
    uint32_t a;
    asm("{ .reg .u64 t; cvta.to.shared.u64 t, %1; cvt.u32.u64 %0, t; }" : "=r"(a) : "l"(p));
    return a;
}
__device__ __forceinline__ void cp16(uint32_t s, const void* g) {
    asm volatile("cp.async.cg.shared.global [%0], [%1], 16;" :: "r"(s), "l"(g));
}
__device__ __forceinline__ void ldsm4(uint32_t* r, uint32_t addr) {
    asm volatile("ldmatrix.sync.aligned.m8n8.x4.shared.b16 {%0,%1,%2,%3}, [%4];"
        : "=r"(r[0]), "=r"(r[1]), "=r"(r[2]), "=r"(r[3]) : "r"(addr));
}
__device__ __forceinline__ void mma16816(float* c, const uint32_t* a, const uint32_t* b) {
    asm volatile("mma.sync.aligned.m16n8k16.row.col.f32.bf16.bf16.f32 "
        "{%0,%1,%2,%3}, {%4,%5,%6,%7}, {%8,%9}, {%0,%1,%2,%3};"
        : "+f"(c[0]), "+f"(c[1]), "+f"(c[2]), "+f"(c[3])
        : "r"(a[0]), "r"(a[1]), "r"(a[2]), "r"(a[3]), "r"(b[0]), "r"(b[1]));
}

// ---------------- fp32 -> bf16 hi/lo split ----------------------------------
__device__ __forceinline__ void split1(float v, __nv_bfloat16& h, __nv_bfloat16& l) {
    h = __float2bfloat16(v);
    l = __float2bfloat16(v - __bfloat162float(h));
}
__device__ __forceinline__ void split_pack(float v0, float v1, unsigned& h2, unsigned& l2) {
    __nv_bfloat16 h0, h1, l0, l1;
    split1(v0, h0, l0); split1(v1, h1, l1);
    h2 = ((unsigned)__bfloat16_as_ushort(h1) << 16) | __bfloat16_as_ushort(h0);
    l2 = ((unsigned)__bfloat16_as_ushort(l1) << 16) | __bfloat16_as_ushort(l0);
}

// ---------------- conversion kernels -----------------------------------------
__global__ void k_cvt_pair(const float* __restrict__ src, __nv_bfloat16* __restrict__ hi,
                           __nv_bfloat16* __restrict__ lo, int n2)
{
    int i = blockIdx.x * blockDim.x + threadIdx.x;
    if (i >= n2) return;
    float2 v = ((const float2*)src)[i];
    unsigned h2, l2; split_pack(v.x, v.y, h2, l2);
    ((unsigned*)hi)[i] = h2; ((unsigned*)lo)[i] = l2;
}

__global__ void k_cvt_wt(const float* __restrict__ W)   // W[1024][512] -> Wt[512][1024]
{
    int i = blockIdx.x * blockDim.x + threadIdx.x;       // 524288
    int n = i >> 10, k = i & 1023;
    float v = W[(size_t)k * FOUT + n];
    split1(v, d_wt_hi[i], d_wt_lo[i]);
}

// ---------------- transpose h -> h^T (per batch) ------------------------------
__global__ void k_tr()
{
    __shared__ __nv_bfloat16 t[32][33];
    const int z = blockIdx.z;
    const int b = z >> 1;
    const __nv_bfloat16* src = (z & 1) ? d_h_lo : d_h_hi;
    __nv_bfloat16*       dst = (z & 1) ? d_ht_lo : d_ht_hi;
    const int f0 = blockIdx.x * 32, n0 = blockIdx.y * 32;
    const int tx = threadIdx.x, ty = threadIdx.y;   // (32,8)
    #pragma unroll
    for (int i = 0; i < 4; i++) {
        int n = n0 + ty + i * 8;
        t[ty + i * 8][tx] = src[(size_t)(b * NN + n) * FOUT + f0 + tx];
    }
    __syncthreads();
    #pragma unroll
    for (int i = 0; i < 4; i++) {
        int f = f0 + ty + i * 8;
        dst[(size_t)(b * FOUT + f) * NN + n0 + tx] = t[tx][ty + i * 8];
    }
}

// ---------------- f1/f2 ------------------------------------------------------
__global__ void k_f12(const float* __restrict__ a)
{
    int row  = (blockIdx.x * blockDim.x + threadIdx.x) >> 5;
    int lane = threadIdx.x & 31;
    if (row >= MTOT) return;
    const __nv_bfloat16* hh = d_h_hi + (size_t)row * FOUT;
    const __nv_bfloat16* hl = d_h_lo + (size_t)row * FOUT;
    float s1 = 0.f, s2 = 0.f;
    for (int k = lane; k < FOUT; k += 32) {
        float hv = __bfloat162float(hh[k]) + __bfloat162float(hl[k]);
        s1 = fmaf(hv, a[k], s1);
        s2 = fmaf(hv, a[FOUT + k], s2);
    }
    #pragma unroll
    for (int o = 16; o; o >>= 1) {
        s1 += __shfl_xor_sync(0xffffffffu, s1, o);
        s2 += __shfl_xor_sync(0xffffffffu, s2, o);
    }
    if (lane == 0) { d_f1[row] = s1; d_f2[row] = s2; }
}

// ---------------- attention numerators (bf16 hi/lo) + 1/rowsum ---------------
__global__ void k_att(const int* __restrict__ adj)
{
    const int row = blockIdx.x;
    const int b   = row >> 10;
    const int tid = threadIdx.x;

    __shared__ float sh[NN];
    __shared__ float red[256];

    const float f1i = d_f1[row];
    const int*   arow = adj + (size_t)row * NN;
    const float* f2b  = d_f2 + b * NN;

    float lmax = -INFINITY;
    for (int j = tid; j < NN; j += 256) {
        float e = f1i + f2b[j];
        e = e > 0.f ? e : ALPHA_SLOPE * e;
        e = (arow[j] > 0) ? e : NEG_INF_F;
        sh[j] = e;
        lmax = fmaxf(lmax, e);
    }
    red[tid] = lmax;
    __syncthreads();
    for (int s = 128; s; s >>= 1) {
        if (tid < s) red[tid] = fmaxf(red[tid], red[tid + s]);
        __syncthreads();
    }
    const float m = red[0];
    __syncthreads();

    float lsum = 0.f;
    __nv_bfloat16* ph = d_att_hi + (size_t)row * NN;
    __nv_bfloat16* pl = d_att_lo + (size_t)row * NN;
    for (int j = tid; j < NN; j += 256) {
        float p = __expf(sh[j] - m);
        __nv_bfloat16 hh, ll; split1(p, hh, ll);
        ph[j] = hh; pl[j] = ll;
        lsum += p;
    }
    red[tid] = lsum;
    __syncthreads();
    for (int s = 128; s; s >>= 1) {
        if (tid < s) red[tid] += red[tid + s];
        __syncthreads();
    }
    if (tid == 0) d_inv[row] = 1.f / red[0];
}

// ---------------- mma.sync GEMM: 128x128 tile, BK=32, SW128 smem, 3 stages ---
// Each smem row = 128B: [hi 32 elems (64B) | lo 32 elems (64B)], SW128 swizzled:
// phys = row*128 + (col16B*16 ^ ((row&7)<<4)). A tile 16KB, B tile 16KB.
#define TILE_B   16384
#define STAGE_B  32768                 // A + B combined tiles
#define NSTAGE   3
#define SM_BYTES (NSTAGE * STAGE_B)    // 98304 -> 2 CTAs/SM

__device__ __forceinline__ uint32_t sw_off(int row, int colb) {
    return (uint32_t)(row * 128 + (colb ^ ((row & 7) << 4)));
}

template<int MODE>
__global__ __launch_bounds__(256, 2)
void k_tc(const float* __restrict__ fcb, float* __restrict__ outp)
{
    extern __shared__ char smem[];
    const uint32_t sb = smem_u32(smem);
    const int tid = threadIdx.x;
    const int wid = tid >> 5, lane = tid & 31;
    const int wm = wid & 1, wn = wid >> 1;       // 2 x 4 warp grid; warp tile 64m x 32n

    const int n0 = blockIdx.x * 128;
    const int m0 = blockIdx.y * 128;             // local row for MODE 2, global else
    const int b  = (MODE == 2) ? blockIdx.z : (m0 >> 10);

    float acc[4][4][4] = {};

    const int NIT = 32;                          // K = 1024, BK = 32

    // ---- precompute per-thread cp.async source offsets (invariant over c) ----
    const __nv_bfloat16 *A1h, *A1l, *A2h, *A2l, *B1h, *B1l;   // A2 = second A source (MODE 3)
    uint32_t lda, ldb;
    if (MODE == 1) {
        lda = FIN; ldb = FIN;
        uint32_t ao = (uint32_t)m0 * FIN, bo = (uint32_t)n0 * FIN;
        A1h = d_x_hi + ao;  A1l = d_x_lo + ao;  A2h = A1h; A2l = A1l;
        B1h = d_wt_hi + bo; B1l = d_wt_lo + bo;
    } else if (MODE == 2) {
        lda = NN; ldb = NN;
        uint32_t ao = (uint32_t)b * NN * NN + (uint32_t)m0 * NN;
        uint32_t bo = (uint32_t)b * FOUT * NN + (uint32_t)n0 * NN;
        A1h = d_att_hi + ao; A1l = d_att_lo + ao; A2h = A1h; A2l = A1l;
        B1h = d_ht_hi + bo;  B1l = d_ht_lo + bo;
    } else {
        lda = FOUT; ldb = 2 * FOUT;
        uint32_t ao = (uint32_t)m0 * FOUT, bo = (uint32_t)n0 * (2 * FOUT);
        A1h = d_agg_hi + ao; A1l = d_agg_lo + ao;
        A2h = d_h_hi + ao;   A2l = d_h_lo + ao;
        B1h = d_fcw_hi + bo; B1l = d_fcw_lo + bo;
    }
    uint32_t a_goff[4], a_dst[4], b_goff[4], b_dst[4];
    bool a_hi[4], b_hi[4];
    #pragma unroll
    for (int i = 0; i < 4; i++) {
        int idx = tid + i * 256;
        int row = idx >> 3, s = idx & 7;
        a_hi[i]   = (s < 4);
        a_goff[i] = (uint32_t)row * lda + (s & 3) * 8;
        a_dst[i]  = sw_off(row, s * 16);
        b_hi[i]   = (s < 4);
        b_goff[i] = (uint32_t)row * ldb + (s & 3) * 8;
        b_dst[i]  = TILE_B + sw_off(row, s * 16);
    }

    auto issue = [&](int c) {
        const uint32_t st = sb + (c % NSTAGE) * STAGE_B;
        const uint32_t ka = (MODE == 3) ? (uint32_t)(c & 15) * 32 : (uint32_t)c * 32;
        const uint32_t kb = (uint32_t)c * 32;
        const __nv_bfloat16* Ah = (MODE == 3 && c >= 16) ? A2h : A1h;
        const __nv_bfloat16* Al = (MODE == 3 && c >= 16) ? A2l : A1l;
        #pragma unroll
        for (int i = 0; i < 4; i++)
            cp16(st + a_dst[i], (a_hi[i] ? Ah : Al) + a_goff[i] + ka);
        #pragma unroll
        for (int i = 0; i < 4; i++)
            cp16(st + b_dst[i], (b_hi[i] ? B1h : B1l) + b_goff[i] + kb);
        asm volatile("cp.async.commit_group;" ::: "memory");
    };

    // ---- per-thread ldmatrix address components (invariant) ----
    const int arow_base = wm * 64 + (lane & 15);
    const int acol_sel  = (lane >> 4) * 16;
    const int brow      = wn * 32 + ((lane >> 4) & 1) * 8 + (lane & 7);  // ntt within pair
    const int bcol_sel  = ((lane >> 3) & 1) * 16;

    issue(0);
    issue(1);
    #pragma unroll 1
    for (int c = 0; c < NIT; c++) {
        if (c == NIT - 1) asm volatile("cp.async.wait_group 0;" ::: "memory");
        else              asm volatile("cp.async.wait_group 1;" ::: "memory");
        __syncthreads();                 // stage c readable; all warps done with the
                                         // buffer (c+2)%3 (last read at iter c-1)
        if (c + 2 < NIT) issue(c + 2);

        const uint32_t base = sb + (c % NSTAGE) * STAGE_B;
        #pragma unroll
        for (int ks = 0; ks < 2; ks++) {
            const int colh = ks * 32;
            // B fragments: one ldsm4 covers two nt tiles
            uint32_t bh[4][2], bl[4][2];
            #pragma unroll
            for (int nt2 = 0; nt2 < 2; nt2++) {
                int row = brow + nt2 * 16;
                uint32_t r[4];
                ldsm4(r, base + TILE_B + sw_off(row, colh + bcol_sel));
                bh[nt2*2][0] = r[0]; bh[nt2*2][1] = r[1];
                bh[nt2*2+1][0] = r[2]; bh[nt2*2+1][1] = r[3];
                ldsm4(r, base + TILE_B + sw_off(row, colh + bcol_sel + 64));
                bl[nt2*2][0] = r[0]; bl[nt2*2][1] = r[1];
                bl[nt2*2+1][0] = r[2]; bl[nt2*2+1][1] = r[3];
            }
            // A fragments: double-buffered across mt (load mt+1 before mt's MMAs)
            uint32_t afr[2][8];
            ldsm4(afr[0],     base + sw_off(arow_base, colh + acol_sel));
            ldsm4(afr[0] + 4, base + sw_off(arow_base, colh + acol_sel + 64));
            #pragma unroll
            for (int mt = 0; mt < 4; mt++) {
                if (mt < 3) {
                    int row = arow_base + (mt + 1) * 16;
                    ldsm4(afr[(mt+1)&1],     base + sw_off(row, colh + acol_sel));
                    ldsm4(afr[(mt+1)&1] + 4, base + sw_off(row, colh + acol_sel + 64));
                }
                const uint32_t* ah = afr[mt & 1];
                const uint32_t* al = ah + 4;
                #pragma unroll
                for (int nt = 0; nt < 4; nt++) mma16816(acc[mt][nt], ah, bh[nt]);
                #pragma unroll
                for (int nt = 0; nt < 4; nt++) mma16816(acc[mt][nt], ah, bl[nt]);
                #pragma unroll
                for (int nt = 0; nt < 4; nt++) mma16816(acc[mt][nt], al, bh[nt]);
            }
        }
        // next iteration's top sync provides the RAW/WAR barrier
    }

    __syncthreads();

    // ---------------- epilogue: direct fragment stores ----------------
    const int g = lane >> 2, tig = lane & 3;
    #pragma unroll
    for (int mt = 0; mt < 4; mt++) {
        const int lr0 = wm * 64 + mt * 16 + g;
        const int lr1 = lr0 + 8;
        float s0 = 1.f, s1 = 1.f;
        if (MODE == 2) {
            s0 = d_inv[b * NN + m0 + lr0];
            s1 = d_inv[b * NN + m0 + lr1];
        }
        #pragma unroll
        for (int nt = 0; nt < 4; nt++) {
            float* c = acc[mt][nt];
            const int ncol = n0 + wn * 32 + nt * 8 + tig * 2;
            if (MODE == 1) {
                unsigned h2, l2;
                split_pack(c[0], c[1], h2, l2);
                size_t o = (size_t)(m0 + lr0) * FOUT + ncol;
                *(unsigned*)(d_h_hi + o) = h2; *(unsigned*)(d_h_lo + o) = l2;
                split_pack(c[2], c[3], h2, l2);
                o = (size_t)(m0 + lr1) * FOUT + ncol;
                *(unsigned*)(d_h_hi + o) = h2; *(unsigned*)(d_h_lo + o) = l2;
            } else if (MODE == 2) {
                unsigned h2, l2;
                split_pack(c[0] * s0, c[1] * s0, h2, l2);
                size_t o = (size_t)(b * NN + m0 + lr0) * FOUT + ncol;
                *(unsigned*)(d_agg_hi + o) = h2; *(unsigned*)(d_agg_lo + o) = l2;
                split_pack(c[2] * s1, c[3] * s1, h2, l2);
                o = (size_t)(b * NN + m0 + lr1) * FOUT + ncol;
                *(unsigned*)(d_agg_hi + o) = h2; *(unsigned*)(d_agg_lo + o) = l2;
            } else {
                float b0 = fcb[ncol], b1 = fcb[ncol + 1];
                float v0 = c[0] + b0, v1 = c[1] + b1;
                v0 = v0 > 0.f ? v0 : expm1f(v0);
                v1 = v1 > 0.f ? v1 : expm1f(v1);
                *(float2*)(outp + (size_t)(m0 + lr0) * FOUT + ncol) = make_float2(v0, v1);
                float v2 = c[2] + b0, v3 = c[3] + b1;
                v2 = v2 > 0.f ? v2 : expm1f(v2);
                v3 = v3 > 0.f ? v3 : expm1f(v3);
                *(float2*)(outp + (size_t)(m0 + lr1) * FOUT + ncol) = make_float2(v2, v3);
            }
        }
    }
}

// ---------------- launch -----------------------------------------------------
extern "C" void kernel_launch(void* const* d_in, const int* in_sizes, int n_in,
                              void* d_out, int out_size)
{
    const float* x   = (const float*)d_in[0];
    const int*   adj = (const int*)  d_in[1];
    const float* W   = (const float*)d_in[2];
    const float* a   = (const float*)d_in[3];
    const float* fcw = (const float*)d_in[4];
    const float* fcb = (const float*)d_in[5];
    float* out = (float*)d_out;

    cudaFuncSetAttribute(k_tc<1>, cudaFuncAttributeMaxDynamicSharedMemorySize, SM_BYTES);
    cudaFuncSetAttribute(k_tc<2>, cudaFuncAttributeMaxDynamicSharedMemorySize, SM_BYTES);
    cudaFuncSetAttribute(k_tc<3>, cudaFuncAttributeMaxDynamicSharedMemorySize, SM_BYTES);

    __nv_bfloat16 *xh, *xl, *fh, *fl;
    cudaGetSymbolAddress((void**)&xh, d_x_hi);
    cudaGetSymbolAddress((void**)&xl, d_x_lo);
    cudaGetSymbolAddress((void**)&fh, d_fcw_hi);
    cudaGetSymbolAddress((void**)&fl, d_fcw_lo);

    // conversions
    k_cvt_pair<<<(MTOT * FIN / 2 + 255) / 256, 256>>>(x, xh, xl, MTOT * FIN / 2);
    k_cvt_wt  <<<(FOUT * FIN + 255) / 256, 256>>>(W);
    k_cvt_pair<<<(FOUT * 2 * FOUT / 2 + 255) / 256, 256>>>(fcw, fh, fl, FOUT * 2 * FOUT / 2);

    // 1) h = x @ W
    k_tc<1><<<dim3(FOUT / 128, MTOT / 128), 256, SM_BYTES>>>(nullptr, nullptr);
    // 1b) h^T per batch (hi & lo)
    k_tr<<<dim3(FOUT / 32, NN / 32, BB * 2), dim3(32, 8)>>>();
    // 2) f1, f2
    k_f12<<<(MTOT * 32) / 256, 256>>>(a);
    // 3) attention numerators + inverse row sums
    k_att<<<MTOT, 256>>>(adj);
    // 4) agg = softmax(att) @ h
    k_tc<2><<<dim3(FOUT / 128, NN / 128, BB), 256, SM_BYTES>>>(nullptr, nullptr);
    // 5) out = elu([agg, h] @ fc_w^T + fc_b)
    k_tc<3><<<dim3(FOUT / 128, MTOT / 128), 256, SM_BYTES>>>(fcb, out);
}

// round 9
// speedup vs baseline: 1.2180x; 1.2180x over previous
#include <cuda_runtime.h>
#include <math.h>
#include <stdint.h>

#define ALPHA_SLOPE 0.2f
#define NEG_INF_F   -9000000000000000.0f

#define BB    16
#define NN    1024
#define FIN   1024
#define FOUT  512
#define MTOT  (BB*NN)        // 16384

// ---------------- scratch: fragment-major tf32 buffers ----------------------
// A-frag layout (m16n8k8 A): per 16m x 8k block, 128 floats: thread t=(m&7)*4+(k&3)
//   holds 16B [a0,a1,a2,a3] = (r,c),(r+8,c),(r,c+4),(r+8,c+4)
// B-frag layout (B n-major [n][k]): per 8n x 8k block, 64 floats: thread t=(n&7)*4+(k&3)
//   holds 8B [b0,b1] = (k,n),(k+4,n)
__device__ float d_x_af  [(size_t)MTOT * FIN];         // 64MB
__device__ float d_wt_bf [(size_t)FOUT * FIN];         // 2MB  (W^T as B-frag)
__device__ float d_fcw_bf[(size_t)FOUT * 2 * FOUT];    // 2MB
__device__ float d_h_lin [(size_t)MTOT * FOUT];        // 32MB (tf32-rounded, linear)
__device__ float d_h_af  [(size_t)MTOT * FOUT];        // 32MB (A-frag, K=512)
__device__ float d_ht_bf [(size_t)BB * FOUT * NN];     // 32MB (h^T B-frag per batch)
__device__ float d_att_af[(size_t)MTOT * NN];          // 64MB (A-frag per batch)
__device__ float d_agg_af[(size_t)MTOT * FOUT];        // 32MB (A-frag, K=512)
__device__ float d_f1 [MTOT];
__device__ float d_f2 [MTOT];
__device__ float d_inv[MTOT];

// ---------------- helpers ----------------------------------------------------
__device__ __forceinline__ uint32_t smem_u32(const void* p) {
    uint32_t a;
    asm("{ .reg .u64 t; cvta.to.shared.u64 t, %1; cvt.u32.u64 %0, t; }" : "=r"(a) : "l"(p));
    return a;
}
__device__ __forceinline__ void cp16(uint32_t s, const void* g) {
    asm volatile("cp.async.cg.shared.global [%0], [%1], 16;" :: "r"(s), "l"(g));
}
__device__ __forceinline__ void lds128(uint32_t* r, uint32_t a) {
    asm volatile("ld.shared.v4.b32 {%0,%1,%2,%3}, [%4];"
        : "=r"(r[0]), "=r"(r[1]), "=r"(r[2]), "=r"(r[3]) : "r"(a));
}
__device__ __forceinline__ void lds64(uint32_t* r, uint32_t a) {
    asm volatile("ld.shared.v2.b32 {%0,%1}, [%2];"
        : "=r"(r[0]), "=r"(r[1]) : "r"(a));
}
__device__ __forceinline__ void mmatf32(float* c, const uint32_t* a, const uint32_t* b) {
    asm volatile("mma.sync.aligned.m16n8k8.row.col.f32.tf32.tf32.f32 "
        "{%0,%1,%2,%3}, {%4,%5,%6,%7}, {%8,%9}, {%0,%1,%2,%3};"
        : "+f"(c[0]), "+f"(c[1]), "+f"(c[2]), "+f"(c[3])
        : "r"(a[0]), "r"(a[1]), "r"(a[2]), "r"(a[3]), "r"(b[0]), "r"(b[1]));
}
__device__ __forceinline__ uint32_t tf32b(float x) {
    uint32_t u;
    asm("cvt.rna.tf32.f32 %0, %1;" : "=r"(u) : "f"(x));
    return u;
}

// fragment offsets (in floats); KB8 = K/8
__device__ __forceinline__ uint32_t afrag_off(uint32_t m, uint32_t k, uint32_t KB8) {
    return ((m >> 4) * KB8 + (k >> 3)) * 128u
         + ((m & 7) * 4 + (k & 3)) * 4u + ((k >> 2) & 1) * 2u + ((m >> 3) & 1);
}
__device__ __forceinline__ uint32_t bfrag_off(uint32_t n, uint32_t k, uint32_t KB8) {
    return ((n >> 3) * KB8 + (k >> 3)) * 64u
         + ((n & 7) * 4 + (k & 3)) * 2u + ((k >> 2) & 1);
}

// ---------------- conversion kernels -----------------------------------------
__global__ void k_cvt_x(const float* __restrict__ x)
{
    uint32_t i = blockIdx.x * 256 + threadIdx.x;     // 16.8M
    uint32_t m = i >> 10, k = i & 1023;
    ((uint32_t*)d_x_af)[afrag_off(m, k, 128)] = tf32b(x[i]);
}
__global__ void k_cvt_wt(const float* __restrict__ W)    // W[1024][512] -> B-frag [n][k]
{
    uint32_t i = blockIdx.x * 256 + threadIdx.x;     // 524288, n fastest
    uint32_t n = i & 511, k = i >> 9;
    ((uint32_t*)d_wt_bf)[bfrag_off(n, k, 128)] = tf32b(W[i]);
}
__global__ void k_cvt_fcw(const float* __restrict__ FCW) // fcw[512][1024] -> B-frag
{
    uint32_t i = blockIdx.x * 256 + threadIdx.x;     // 524288, k fastest
    uint32_t n = i >> 10, k = i & 1023;
    ((uint32_t*)d_fcw_bf)[bfrag_off(n, k, 128)] = tf32b(FCW[i]);
}

// ---------------- h -> h^T B-frag (per batch) ---------------------------------
__global__ void k_trB()
{
    uint32_t i = blockIdx.x * 256 + threadIdx.x;     // 8.4M, f fastest
    uint32_t mg = i >> 9, f = i & 511;
    uint32_t b = mg >> 10, ml = mg & 1023;
    ((uint32_t*)d_ht_bf)[b * (FOUT * NN) + bfrag_off(f, ml, 128)] =
        ((const uint32_t*)d_h_lin)[i];
}

// ---------------- f1/f2 ------------------------------------------------------
__global__ void k_f12(const float* __restrict__ a)
{
    int row  = (blockIdx.x * blockDim.x + threadIdx.x) >> 5;
    int lane = threadIdx.x & 31;
    if (row >= MTOT) return;
    const float* hr = d_h_lin + (size_t)row * FOUT;
    float s1 = 0.f, s2 = 0.f;
    for (int k = lane; k < FOUT; k += 32) {
        float hv = hr[k];
        s1 = fmaf(hv, a[k], s1);
        s2 = fmaf(hv, a[FOUT + k], s2);
    }
    #pragma unroll
    for (int o = 16; o; o >>= 1) {
        s1 += __shfl_xor_sync(0xffffffffu, s1, o);
        s2 += __shfl_xor_sync(0xffffffffu, s2, o);
    }
    if (lane == 0) { d_f1[row] = s1; d_f2[row] = s2; }
}

// ---------------- attention numerators (A-frag tf32) + 1/rowsum ---------------
__global__ void k_att(const int* __restrict__ adj)
{
    const int row  = blockIdx.x;
    const int b    = row >> 10;
    const uint32_t iloc = row & 1023;
    const int tid  = threadIdx.x;

    __shared__ float sh[NN];
    __shared__ float red[256];

    const float f1i = d_f1[row];
    const int*   arow = adj + (size_t)row * NN;
    const float* f2b  = d_f2 + b * NN;

    float lmax = -INFINITY;
    for (int j = tid; j < NN; j += 256) {
        float e = f1i + f2b[j];
        e = e > 0.f ? e : ALPHA_SLOPE * e;
        e = (arow[j] > 0) ? e : NEG_INF_F;
        sh[j] = e;
        lmax = fmaxf(lmax, e);
    }
    red[tid] = lmax;
    __syncthreads();
    for (int s = 128; s; s >>= 1) {
        if (tid < s) red[tid] = fmaxf(red[tid], red[tid + s]);
        __syncthreads();
    }
    const float m = red[0];
    __syncthreads();

    float lsum = 0.f;
    uint32_t* pA = (uint32_t*)d_att_af + (uint32_t)b * (NN * NN);
    for (int j = tid; j < NN; j += 256) {
        float p = __expf(sh[j] - m);
        pA[afrag_off(iloc, (uint32_t)j, 128)] = tf32b(p);
        lsum += p;
    }
    red[tid] = lsum;
    __syncthreads();
    for (int s = 128; s; s >>= 1) {
        if (tid < s) red[tid] += red[tid + s];
        __syncthreads();
    }
    if (tid == 0) d_inv[row] = 1.f / red[0];
}

// ---------------- tf32 mma GEMM: 128x128 tile, BK=32, frag-major smem --------
// smem stage: A 16KB (32 blocks x 512B, [mb][kb]) + B 16KB (64 blocks x 256B, [nb][kb])
#define A_TILE_B 16384
#define STAGE_B  32768
#define NSTAGE   3
#define SM_BYTES (NSTAGE * STAGE_B)    // 98304 -> 2 CTAs/SM

template<int MODE>
__global__ __launch_bounds__(256, 2)
void k_tc(const float* __restrict__ fcb, float* __restrict__ outp)
{
    extern __shared__ char smem[];
    const uint32_t sb = smem_u32(smem);
    const int tid = threadIdx.x;
    const int wid = tid >> 5, lane = tid & 31;
    const int wm = wid & 1, wn = wid >> 1;       // warp tile 64m x 32n

    const int n0 = blockIdx.x * 128;
    const int m0 = blockIdx.y * 128;             // local row for MODE 2, global else
    const int b  = (MODE == 2) ? blockIdx.z : (m0 >> 10);

    float acc[4][4][4] = {};
    const int NIT = 32;                          // K = 1024, BK = 32

    // ---- sources ----
    const float *Ap1, *Ap2, *Bp;
    uint32_t KA8;
    if (MODE == 1) {
        Ap1 = d_x_af;  Ap2 = Ap1; Bp = d_wt_bf;  KA8 = 128;
    } else if (MODE == 2) {
        Ap1 = d_att_af + (uint32_t)b * (NN * NN); Ap2 = Ap1;
        Bp  = d_ht_bf  + (uint32_t)b * (FOUT * NN); KA8 = 128;
    } else {
        Ap1 = d_agg_af; Ap2 = d_h_af; Bp = d_fcw_bf; KA8 = 64;
    }

    // ---- per-thread cp.async invariants ----
    // A: 1024 chunks of 16B; chunk idx -> block=idx>>5 (mb=blk>>2, kb=blk&3), word=(idx&31)
    uint32_t a_base[4], a_dst[4], b_base[4], b_dst[4];
    #pragma unroll
    for (int j = 0; j < 4; j++) {
        uint32_t idx = tid + j * 256;
        uint32_t blk = idx >> 5, w = idx & 31;
        uint32_t mb = blk >> 2, kb = blk & 3;
        a_base[j] = (((uint32_t)(m0 >> 4) + mb) * KA8 + kb) * 128u + w * 4u;
        a_dst[j]  = blk * 512u + w * 16u;
        blk = idx >> 4; w = idx & 15;
        uint32_t nb = blk >> 2, kbb = blk & 3;
        b_base[j] = (((uint32_t)(n0 >> 3) + nb) * 128u + kbb) * 64u + w * 4u;
        b_dst[j]  = A_TILE_B + blk * 256u + w * 16u;
    }

    auto issue = [&](int c) {
        const uint32_t st = sb + (c % NSTAGE) * STAGE_B;
        const float* Ap = (MODE == 3 && c >= 16) ? Ap2 : Ap1;
        const uint32_t ca = (MODE == 3) ? (uint32_t)(c & 15) * 512u : (uint32_t)c * 512u;
        const uint32_t cb = (uint32_t)c * 256u;
        #pragma unroll
        for (int j = 0; j < 4; j++) cp16(st + a_dst[j], Ap + a_base[j] + ca);
        #pragma unroll
        for (int j = 0; j < 4; j++) cp16(st + b_dst[j], Bp + b_base[j] + cb);
        asm volatile("cp.async.commit_group;" ::: "memory");
    };

    const uint32_t a_lds = (uint32_t)lane * 16u;
    const uint32_t b_lds = A_TILE_B + (uint32_t)lane * 8u;

    issue(0);
    issue(1);
    #pragma unroll 1
    for (int c = 0; c < NIT; c++) {
        if (c == NIT - 1) asm volatile("cp.async.wait_group 0;" ::: "memory");
        else              asm volatile("cp.async.wait_group 1;" ::: "memory");
        __syncthreads();
        if (c + 2 < NIT) issue(c + 2);

        const uint32_t base = sb + (c % NSTAGE) * STAGE_B;
        #pragma unroll
        for (int ks = 0; ks < 4; ks++) {
            uint32_t bf[4][2];
            #pragma unroll
            for (int nt = 0; nt < 4; nt++)
                lds64(bf[nt], base + b_lds + ((wn * 4 + nt) * 4 + ks) * 256u);
            #pragma unroll
            for (int mt = 0; mt < 4; mt++) {
                uint32_t af[4];
                lds128(af, base + a_lds + ((wm * 4 + mt) * 4 + ks) * 512u);
                #pragma unroll
                for (int nt = 0; nt < 4; nt++) mmatf32(acc[mt][nt], af, bf[nt]);
            }
        }
    }

    __syncthreads();

    // ---------------- epilogue ----------------
    const int g = lane >> 2, tig = lane & 3;
    #pragma unroll
    for (int mt = 0; mt < 4; mt++) {
        const int lr0 = wm * 64 + mt * 16 + g;
        const int lr1 = lr0 + 8;
        float s0 = 1.f, s1 = 1.f;
        if (MODE == 2) {
            s0 = d_inv[b * NN + m0 + lr0];
            s1 = d_inv[b * NN + m0 + lr1];
        }
        #pragma unroll
        for (int nt = 0; nt < 4; nt++) {
            float* c = acc[mt][nt];
            const uint32_t ncol = n0 + wn * 32 + nt * 8 + tig * 2;
            if (MODE == 1) {
                const uint32_t m0g = m0 + lr0, m1g = m0 + lr1;
                uint32_t r0 = tf32b(c[0]), r1 = tf32b(c[1]);
                uint32_t r2 = tf32b(c[2]), r3 = tf32b(c[3]);
                *(uint2*)((uint32_t*)d_h_lin + (size_t)m0g * FOUT + ncol) = make_uint2(r0, r1);
                *(uint2*)((uint32_t*)d_h_lin + (size_t)m1g * FOUT + ncol) = make_uint2(r2, r3);
                uint32_t* ha = (uint32_t*)d_h_af;
                ha[afrag_off(m0g, ncol,     64)] = r0;
                ha[afrag_off(m0g, ncol + 1, 64)] = r1;
                ha[afrag_off(m1g, ncol,     64)] = r2;
                ha[afrag_off(m1g, ncol + 1, 64)] = r3;
            } else if (MODE == 2) {
                const uint32_t m0g = b * NN + m0 + lr0, m1g = b * NN + m0 + lr1;
                uint32_t* ga = (uint32_t*)d_agg_af;
                ga[afrag_off(m0g, ncol,     64)] = tf32b(c[0] * s0);
                ga[afrag_off(m0g, ncol + 1, 64)] = tf32b(c[1] * s0);
                ga[afrag_off(m1g, ncol,     64)] = tf32b(c[2] * s1);
                ga[afrag_off(m1g, ncol + 1, 64)] = tf32b(c[3] * s1);
            } else {
                float b0 = fcb[ncol], b1 = fcb[ncol + 1];
                float v0 = c[0] + b0, v1 = c[1] + b1;
                v0 = v0 > 0.f ? v0 : expm1f(v0);
                v1 = v1 > 0.f ? v1 : expm1f(v1);
                *(float2*)(outp + (size_t)(m0 + lr0) * FOUT + ncol) = make_float2(v0, v1);
                float v2 = c[2] + b0, v3 = c[3] + b1;
                v2 = v2 > 0.f ? v2 : expm1f(v2);
                v3 = v3 > 0.f ? v3 : expm1f(v3);
                *(float2*)(outp + (size_t)(m0 + lr1) * FOUT + ncol) = make_float2(v2, v3);
            }
        }
    }
}

// ---------------- launch -----------------------------------------------------
extern "C" void kernel_launch(void* const* d_in, const int* in_sizes, int n_in,
                              void* d_out, int out_size)
{
    const float* x   = (const float*)d_in[0];
    const int*   adj = (const int*)  d_in[1];
    const float* W   = (const float*)d_in[2];
    const float* a   = (const float*)d_in[3];
    const float* fcw = (const float*)d_in[4];
    const float* fcb = (const float*)d_in[5];
    float* out = (float*)d_out;

    cudaFuncSetAttribute(k_tc<1>, cudaFuncAttributeMaxDynamicSharedMemorySize, SM_BYTES);
    cudaFuncSetAttribute(k_tc<2>, cudaFuncAttributeMaxDynamicSharedMemorySize, SM_BYTES);
    cudaFuncSetAttribute(k_tc<3>, cudaFuncAttributeMaxDynamicSharedMemorySize, SM_BYTES);

    // conversions to fragment-major tf32
    k_cvt_x  <<<(MTOT * FIN) / 256, 256>>>(x);
    k_cvt_wt <<<(FIN * FOUT) / 256, 256>>>(W);
    k_cvt_fcw<<<(FOUT * 2 * FOUT) / 256, 256>>>(fcw);

    // 1) h = x @ W  (writes h linear + h A-frag)
    k_tc<1><<<dim3(FOUT / 128, MTOT / 128), 256, SM_BYTES>>>(nullptr, nullptr);
    // 1b) h^T per batch (B-frag)
    k_trB<<<(MTOT * FOUT) / 256, 256>>>();
    // 2) f1, f2
    k_f12<<<(MTOT * 32) / 256, 256>>>(a);
    // 3) attention numerators + inverse row sums
    k_att<<<MTOT, 256>>>(adj);
    // 4) agg = softmax(att) @ h
    k_tc<2><<<dim3(FOUT / 128, NN / 128, BB), 256, SM_BYTES>>>(nullptr, nullptr);
    // 5) out = elu([agg, h] @ fc_w^T + fc_b)
    k_tc<3><<<dim3(FOUT / 128, MTOT / 128), 256, SM_BYTES>>>(fcb, out);
}

// round 10
// speedup vs baseline: 1.2564x; 1.0316x over previous
#include <cuda_runtime.h>
#include <math.h>
#include <stdint.h>

#define ALPHA_SLOPE 0.2f
#define NEG_INF_F   -9000000000000000.0f

#define BB    16
#define NN    1024
#define FIN   1024
#define FOUT  512
#define MTOT  (BB*NN)        // 16384

// ---------------- scratch: fragment-major tf32 buffers ----------------------
// A-frag (m16n8k8 A): per 16m x 8k block, 128 floats: thread t=(m&7)*4+(k&3)
//   holds 16B [a0,a1,a2,a3] = (r,c),(r+8,c),(r,c+4),(r+8,c+4)
// B-frag (B n-major [n][k]): per 8n x 8k block, 64 floats: thread t=(n&7)*4+(k&3)
//   holds 8B [b0,b1] = (k,n),(k+4,n)
__device__ float d_x_af  [(size_t)MTOT * FIN];         // 64MB
__device__ float d_wt_bf [(size_t)FOUT * FIN];         // 2MB  (W^T as B-frag)
__device__ float d_fcw_bf[(size_t)FOUT * 2 * FOUT];    // 2MB
__device__ float d_h_lin [(size_t)MTOT * FOUT];        // 32MB (tf32-rounded, linear)
__device__ float d_h_af  [(size_t)MTOT * FOUT];        // 32MB (A-frag, K=512)
__device__ float d_ht_bf [(size_t)BB * FOUT * NN];     // 32MB (h^T B-frag per batch)
__device__ float d_att_af[(size_t)MTOT * NN];          // 64MB (A-frag per batch)
__device__ float d_agg_af[(size_t)MTOT * FOUT];        // 32MB (A-frag, K=512)
__device__ float d_f1 [MTOT];
__device__ float d_f2 [MTOT];
__device__ float d_inv[MTOT];

// ---------------- helpers ----------------------------------------------------
__device__ __forceinline__ uint32_t smem_u32(const void* p) {
    uint32_t a;
    asm("{ .reg .u64 t; cvta.to.shared.u64 t, %1; cvt.u32.u64 %0, t; }" : "=r"(a) : "l"(p));
    return a;
}
__device__ __forceinline__ void cp16(uint32_t s, const void* g) {
    asm volatile("cp.async.cg.shared.global [%0], [%1], 16;" :: "r"(s), "l"(g));
}
__device__ __forceinline__ void lds128(uint32_t* r, uint32_t a) {
    asm volatile("ld.shared.v4.b32 {%0,%1,%2,%3}, [%4];"
        : "=r"(r[0]), "=r"(r[1]), "=r"(r[2]), "=r"(r[3]) : "r"(a));
}
__device__ __forceinline__ void lds64(uint32_t* r, uint32_t a) {
    asm volatile("ld.shared.v2.b32 {%0,%1}, [%2];"
        : "=r"(r[0]), "=r"(r[1]) : "r"(a));
}
__device__ __forceinline__ void mmatf32(float* c, const uint32_t* a, const uint32_t* b) {
    asm volatile("mma.sync.aligned.m16n8k8.row.col.f32.tf32.tf32.f32 "
        "{%0,%1,%2,%3}, {%4,%5,%6,%7}, {%8,%9}, {%0,%1,%2,%3};"
        : "+f"(c[0]), "+f"(c[1]), "+f"(c[2]), "+f"(c[3])
        : "r"(a[0]), "r"(a[1]), "r"(a[2]), "r"(a[3]), "r"(b[0]), "r"(b[1]));
}
__device__ __forceinline__ uint32_t tf32b(float x) {
    uint32_t u;
    asm("cvt.rna.tf32.f32 %0, %1;" : "=r"(u) : "f"(x));
    return u;
}

// fragment offsets (in floats); KB8 = K/8
__device__ __forceinline__ uint32_t afrag_off(uint32_t m, uint32_t k, uint32_t KB8) {
    return ((m >> 4) * KB8 + (k >> 3)) * 128u
         + ((m & 7) * 4 + (k & 3)) * 4u + ((k >> 2) & 1) * 2u + ((m >> 3) & 1);
}
__device__ __forceinline__ uint32_t bfrag_off(uint32_t n, uint32_t k, uint32_t KB8) {
    return ((n >> 3) * KB8 + (k >> 3)) * 64u
         + ((n & 7) * 4 + (k & 3)) * 2u + ((k >> 2) & 1);
}

// ---------------- conversion kernels -----------------------------------------
__global__ void k_cvt_x(const float* __restrict__ x)
{
    uint32_t i = blockIdx.x * 256 + threadIdx.x;     // 16.8M
    uint32_t m = i >> 10, k = i & 1023;
    ((uint32_t*)d_x_af)[afrag_off(m, k, 128)] = tf32b(x[i]);
}
__global__ void k_cvt_wt(const float* __restrict__ W)    // W[1024][512] -> B-frag [n][k]
{
    uint32_t i = blockIdx.x * 256 + threadIdx.x;     // 524288, n fastest
    uint32_t n = i & 511, k = i >> 9;
    ((uint32_t*)d_wt_bf)[bfrag_off(n, k, 128)] = tf32b(W[i]);
}
__global__ void k_cvt_fcw(const float* __restrict__ FCW) // fcw[512][1024] -> B-frag
{
    uint32_t i = blockIdx.x * 256 + threadIdx.x;     // 524288, k fastest
    uint32_t n = i >> 10, k = i & 1023;
    ((uint32_t*)d_fcw_bf)[bfrag_off(n, k, 128)] = tf32b(FCW[i]);
}

// ---------------- h -> h^T B-frag (per batch) ---------------------------------
__global__ void k_trB()
{
    uint32_t i = blockIdx.x * 256 + threadIdx.x;     // 8.4M, f fastest
    uint32_t mg = i >> 9, f = i & 511;
    uint32_t b = mg >> 10, ml = mg & 1023;
    ((uint32_t*)d_ht_bf)[b * (FOUT * NN) + bfrag_off(f, ml, 128)] =
        ((const uint32_t*)d_h_lin)[i];
}

// ---------------- f1/f2 ------------------------------------------------------
__global__ void k_f12(const float* __restrict__ a)
{
    int row  = (blockIdx.x * blockDim.x + threadIdx.x) >> 5;
    int lane = threadIdx.x & 31;
    if (row >= MTOT) return;
    const float* hr = d_h_lin + (size_t)row * FOUT;
    float s1 = 0.f, s2 = 0.f;
    for (int k = lane; k < FOUT; k += 32) {
        float hv = hr[k];
        s1 = fmaf(hv, a[k], s1);
        s2 = fmaf(hv, a[FOUT + k], s2);
    }
    #pragma unroll
    for (int o = 16; o; o >>= 1) {
        s1 += __shfl_xor_sync(0xffffffffu, s1, o);
        s2 += __shfl_xor_sync(0xffffffffu, s2, o);
    }
    if (lane == 0) { d_f1[row] = s1; d_f2[row] = s2; }
}

// ---------------- attention numerators (A-frag tf32) + 1/rowsum ---------------
__global__ void k_att(const int* __restrict__ adj)
{
    const int row  = blockIdx.x;
    const int b    = row >> 10;
    const uint32_t iloc = row & 1023;
    const int tid  = threadIdx.x;

    __shared__ float sh[NN];
    __shared__ float red[256];

    const float f1i = d_f1[row];
    const int*   arow = adj + (size_t)row * NN;
    const float* f2b  = d_f2 + b * NN;

    float lmax = -INFINITY;
    for (int j = tid; j < NN; j += 256) {
        float e = f1i + f2b[j];
        e = e > 0.f ? e : ALPHA_SLOPE * e;
        e = (arow[j] > 0) ? e : NEG_INF_F;
        sh[j] = e;
        lmax = fmaxf(lmax, e);
    }
    red[tid] = lmax;
    __syncthreads();
    for (int s = 128; s; s >>= 1) {
        if (tid < s) red[tid] = fmaxf(red[tid], red[tid + s]);
        __syncthreads();
    }
    const float m = red[0];
    __syncthreads();

    float lsum = 0.f;
    uint32_t* pA = (uint32_t*)d_att_af + (uint32_t)b * (NN * NN);
    for (int j = tid; j < NN; j += 256) {
        float p = __expf(sh[j] - m);
        pA[afrag_off(iloc, (uint32_t)j, 128)] = tf32b(p);
        lsum += p;
    }
    red[tid] = lsum;
    __syncthreads();
    for (int s = 128; s; s >>= 1) {
        if (tid < s) red[tid] += red[tid + s];
        __syncthreads();
    }
    if (tid == 0) d_inv[row] = 1.f / red[0];
}

// ---------------- tf32 mma GEMM: 128x128 tile, 4 warps of 64x64, BK=32 -------
// smem stage: A 16KB (32 blocks x 512B, [mb][kb]) + B 16KB (64 blocks x 256B, [nb][kb])
#define A_TILE_B 16384
#define STAGE_B  32768
#define NSTAGE   3
#define SM_BYTES (NSTAGE * STAGE_B)    // 98304 -> 2 CTAs/SM

template<int MODE>
__global__ __launch_bounds__(128, 2)
void k_tc(const float* __restrict__ fcb, float* __restrict__ outp)
{
    extern __shared__ char smem[];
    const uint32_t sb = smem_u32(smem);
    const int tid = threadIdx.x;
    const int wid = tid >> 5, lane = tid & 31;
    const int wm = wid & 1, wn = wid >> 1;       // 2 x 2 warp grid; warp tile 64m x 64n

    const int n0 = blockIdx.x * 128;
    const int m0 = blockIdx.y * 128;             // local row for MODE 2, global else
    const int b  = (MODE == 2) ? blockIdx.z : (m0 >> 10);

    float acc[4][8][4] = {};
    const int NIT = 32;                          // K = 1024, BK = 32

    // ---- sources ----
    const float *Ap1, *Ap2, *Bp;
    uint32_t KA8;
    if (MODE == 1) {
        Ap1 = d_x_af;  Ap2 = Ap1; Bp = d_wt_bf;  KA8 = 128;
    } else if (MODE == 2) {
        Ap1 = d_att_af + (uint32_t)b * (NN * NN); Ap2 = Ap1;
        Bp  = d_ht_bf  + (uint32_t)b * (FOUT * NN); KA8 = 128;
    } else {
        Ap1 = d_agg_af; Ap2 = d_h_af; Bp = d_fcw_bf; KA8 = 64;
    }

    // ---- per-thread cp.async invariants (j-strided from base) ----
    uint32_t a_base0, a_dst0, b_base0, b_dst0;
    {
        uint32_t blk = (uint32_t)tid >> 5, w = (uint32_t)tid & 31;
        uint32_t mb = blk >> 2, kb = blk & 3;
        a_base0 = (((uint32_t)(m0 >> 4) + mb) * KA8 + kb) * 128u + w * 4u;
        a_dst0  = blk * 512u + w * 16u;
        blk = (uint32_t)tid >> 4; w = (uint32_t)tid & 15;
        uint32_t nb = blk >> 2, kbb = blk & 3;
        b_base0 = (((uint32_t)(n0 >> 3) + nb) * 128u + kbb) * 64u + w * 4u;
        b_dst0  = A_TILE_B + blk * 256u + w * 16u;
    }
    const uint32_t a_bstride = KA8 * 128u;       // +1 mb block per j

    auto issue = [&](int c) {
        const uint32_t st = sb + (c % NSTAGE) * STAGE_B;
        const float* Ap = (MODE == 3 && c >= 16) ? Ap2 : Ap1;
        const uint32_t ca = (MODE == 3) ? (uint32_t)(c & 15) * 512u : (uint32_t)c * 512u;
        const uint32_t cb = (uint32_t)c * 256u;
        #pragma unroll
        for (uint32_t j = 0; j < 8; j++)
            cp16(st + a_dst0 + j * 2048u, Ap + a_base0 + j * a_bstride + ca);
        #pragma unroll
        for (uint32_t j = 0; j < 8; j++)
            cp16(st + b_dst0 + j * 2048u, Bp + b_base0 + j * 16384u + cb);
        asm volatile("cp.async.commit_group;" ::: "memory");
    };

    const uint32_t a_lds = (uint32_t)lane * 16u;
    const uint32_t b_lds = A_TILE_B + (uint32_t)lane * 8u;

    issue(0);
    issue(1);
    #pragma unroll 1
    for (int c = 0; c < NIT; c++) {
        if (c == NIT - 1) asm volatile("cp.async.wait_group 0;" ::: "memory");
        else              asm volatile("cp.async.wait_group 1;" ::: "memory");
        __syncthreads();
        if (c + 2 < NIT) issue(c + 2);

        const uint32_t base = sb + (c % NSTAGE) * STAGE_B;
        #pragma unroll
        for (int ks = 0; ks < 4; ks++) {
            uint32_t bf[8][2];
            #pragma unroll
            for (int nt = 0; nt < 8; nt++)
                lds64(bf[nt], base + b_lds + ((wn * 8 + nt) * 4 + ks) * 256u);
            #pragma unroll
            for (int mt = 0; mt < 4; mt++) {
                uint32_t af[4];
                lds128(af, base + a_lds + ((wm * 4 + mt) * 4 + ks) * 512u);
                #pragma unroll
                for (int nt = 0; nt < 8; nt++) mmatf32(acc[mt][nt], af, bf[nt]);
            }
        }
    }

    __syncthreads();

    // ---------------- epilogue ----------------
    const int g = lane >> 2, tig = lane & 3;
    #pragma unroll
    for (int mt = 0; mt < 4; mt++) {
        const int lr0 = wm * 64 + mt * 16 + g;
        const int lr1 = lr0 + 8;
        float s0 = 1.f, s1 = 1.f;
        if (MODE == 2) {
            s0 = d_inv[b * NN + m0 + lr0];
            s1 = d_inv[b * NN + m0 + lr1];
        }
        #pragma unroll
        for (int nt = 0; nt < 8; nt++) {
            float* c = acc[mt][nt];
            const uint32_t ncol = n0 + wn * 64 + nt * 8 + tig * 2;
            if (MODE == 1) {
                const uint32_t m0g = m0 + lr0, m1g = m0 + lr1;
                uint32_t r0 = tf32b(c[0]), r1 = tf32b(c[1]);
                uint32_t r2 = tf32b(c[2]), r3 = tf32b(c[3]);
                *(uint2*)((uint32_t*)d_h_lin + (size_t)m0g * FOUT + ncol) = make_uint2(r0, r1);
                *(uint2*)((uint32_t*)d_h_lin + (size_t)m1g * FOUT + ncol) = make_uint2(r2, r3);
                uint32_t* ha = (uint32_t*)d_h_af;
                ha[afrag_off(m0g, ncol,     64)] = r0;
                ha[afrag_off(m0g, ncol + 1, 64)] = r1;
                ha[afrag_off(m1g, ncol,     64)] = r2;
                ha[afrag_off(m1g, ncol + 1, 64)] = r3;
            } else if (MODE == 2) {
                const uint32_t m0g = b * NN + m0 + lr0, m1g = b * NN + m0 + lr1;
                uint32_t* ga = (uint32_t*)d_agg_af;
                ga[afrag_off(m0g, ncol,     64)] = tf32b(c[0] * s0);
                ga[afrag_off(m0g, ncol + 1, 64)] = tf32b(c[1] * s0);
                ga[afrag_off(m1g, ncol,     64)] = tf32b(c[2] * s1);
                ga[afrag_off(m1g, ncol + 1, 64)] = tf32b(c[3] * s1);
            } else {
                float b0 = fcb[ncol], b1 = fcb[ncol + 1];
                float v0 = c[0] + b0, v1 = c[1] + b1;
                v0 = v0 > 0.f ? v0 : expm1f(v0);
                v1 = v1 > 0.f ? v1 : expm1f(v1);
                *(float2*)(outp + (size_t)(m0 + lr0) * FOUT + ncol) = make_float2(v0, v1);
                float v2 = c[2] + b0, v3 = c[3] + b1;
                v2 = v2 > 0.f ? v2 : expm1f(v2);
                v3 = v3 > 0.f ? v3 : expm1f(v3);
                *(float2*)(outp + (size_t)(m0 + lr1) * FOUT + ncol) = make_float2(v2, v3);
            }
        }
    }
}

// ---------------- launch -----------------------------------------------------
extern "C" void kernel_launch(void* const* d_in, const int* in_sizes, int n_in,
                              void* d_out, int out_size)
{
    const float* x   = (const float*)d_in[0];
    const int*   adj = (const int*)  d_in[1];
    const float* W   = (const float*)d_in[2];
    const float* a   = (const float*)d_in[3];
    const float* fcw = (const float*)d_in[4];
    const float* fcb = (const float*)d_in[5];
    float* out = (float*)d_out;

    cudaFuncSetAttribute(k_tc<1>, cudaFuncAttributeMaxDynamicSharedMemorySize, SM_BYTES);
    cudaFuncSetAttribute(k_tc<2>, cudaFuncAttributeMaxDynamicSharedMemorySize, SM_BYTES);
    cudaFuncSetAttribute(k_tc<3>, cudaFuncAttributeMaxDynamicSharedMemorySize, SM_BYTES);

    // conversions to fragment-major tf32
    k_cvt_x  <<<(MTOT * FIN) / 256, 256>>>(x);
    k_cvt_wt <<<(FIN * FOUT) / 256, 256>>>(W);
    k_cvt_fcw<<<(FOUT * 2 * FOUT) / 256, 256>>>(fcw);

    // 1) h = x @ W  (writes h linear + h A-frag)
    k_tc<1><<<dim3(FOUT / 128, MTOT / 128), 128, SM_BYTES>>>(nullptr, nullptr);
    // 1b) h^T per batch (B-frag)
    k_trB<<<(MTOT * FOUT) / 256, 256>>>();
    // 2) f1, f2
    k_f12<<<(MTOT * 32) / 256, 256>>>(a);
    // 3) attention numerators + inverse row sums
    k_att<<<MTOT, 256>>>(adj);
    // 4) agg = softmax(att) @ h
    k_tc<2><<<dim3(FOUT / 128, NN / 128, BB), 128, SM_BYTES>>>(nullptr, nullptr);
    // 5) out = elu([agg, h] @ fc_w^T + fc_b)
    k_tc<3><<<dim3(FOUT / 128, MTOT / 128), 128, SM_BYTES>>>(fcb, out);
}